// round 2
// baseline (speedup 1.0000x reference)
#include <cuda_runtime.h>
#include <cstdint>

// Problem constants (fixed by the reference)
#define N_NODES 50000
#define FDIM    64
#define PER     8
#define E_EDGES 800000
#define KDIM    128      // 2*FDIM (concat Xp | Yp)
#define NG      3        // gates used: i, c, o  (f gate is dead since C=0)

// ---------------- scratch (static device memory: no allocs allowed) ----------
__device__ float g_Xt[(size_t)PER * N_NODES * FDIM];   // [p][n][f]  102.4 MB
__device__ float g_Yt[(size_t)PER * N_NODES * FDIM];   // [p][n][f]  102.4 MB
__device__ float g_deg[N_NODES];
__device__ float g_wn[E_EDGES];
__device__ float g_W[KDIM * NG * FDIM];                // [k][g][j]
__device__ float g_bias[NG * FDIM];                    // combined bx+bh+bg per gate
__device__ float g_wc2[FDIM];                          // peephole for o-gate

// ---------------- helpers ----------------------------------------------------
__device__ __forceinline__ float sigmoid_f(float x) { return 1.0f / (1.0f + __expf(-x)); }
__device__ __forceinline__ float tanh_f(float x)    { return 1.0f - 2.0f / (__expf(2.0f * x) + 1.0f); }

// ---------------- kernels ----------------------------------------------------

// Zero g_Yt (all periods) and g_deg. grid-stride float4.
__global__ void zero_kernel() {
    size_t total4 = (size_t)PER * N_NODES * FDIM / 4;
    size_t stride = (size_t)gridDim.x * blockDim.x;
    float4 z = make_float4(0.f, 0.f, 0.f, 0.f);
    for (size_t i = (size_t)blockIdx.x * blockDim.x + threadIdx.x; i < total4; i += stride) {
        reinterpret_cast<float4*>(g_Yt)[i] = z;
    }
    size_t deg4 = N_NODES / 4;
    for (size_t i = (size_t)blockIdx.x * blockDim.x + threadIdx.x; i < deg4; i += stride) {
        reinterpret_cast<float4*>(g_deg)[i] = z;
    }
}

// Transpose X[n][f][p] -> g_Xt[p][n][f]
__global__ void transpose_kernel(const float* __restrict__ X) {
    int idx = blockIdx.x * blockDim.x + threadIdx.x;   // n*FDIM + f
    if (idx >= N_NODES * FDIM) return;
    int n = idx >> 6;
    int f = idx & 63;
    const float4* xp = reinterpret_cast<const float4*>(X + (size_t)n * FDIM * PER + (size_t)f * PER);
    float4 a = xp[0], b = xp[1];
    float v[PER] = {a.x, a.y, a.z, a.w, b.x, b.y, b.z, b.w};
#pragma unroll
    for (int p = 0; p < PER; p++) {
        g_Xt[(size_t)p * N_NODES * FDIM + (size_t)n * FDIM + f] = v[p];
    }
}

// deg[src] += w   (segment_sum over src)
__global__ void deg_kernel(const int* __restrict__ ei, const float* __restrict__ ew) {
    int e = blockIdx.x * blockDim.x + threadIdx.x;
    if (e >= E_EDGES) return;
    atomicAdd(&g_deg[ei[e]], ew[e]);
}

// wn[e] = -dis[src]*w*dis[dst]
__global__ void wn_kernel(const int* __restrict__ ei, const float* __restrict__ ew) {
    int e = blockIdx.x * blockDim.x + threadIdx.x;
    if (e >= E_EDGES) return;
    int s = ei[e];
    int d = ei[E_EDGES + e];
    float ds = g_deg[s], dd = g_deg[d];
    float is = (ds > 0.f) ? rsqrtf(fmaxf(ds, 1e-12f)) : 0.f;
    float id = (dd > 0.f) ? rsqrtf(fmaxf(dd, 1e-12f)) : 0.f;
    g_wn[e] = -is * ew[e] * id;
}

// Y[p][dst][f] += wn[e] * X[p][src][f]   — 16 threads per edge, float4 each.
// blockIdx.z = period (keeps per-period 12.8MB working set hot in L2 per wave).
__global__ void scatter_kernel(const int* __restrict__ ei) {
    int t = blockIdx.x * blockDim.x + threadIdx.x;
    int e = t >> 4;
    if (e >= E_EDGES) return;
    int l = (t & 15) << 2;        // feature base (0..60 step 4)
    int p = blockIdx.z;
    int s = ei[e];
    int d = ei[E_EDGES + e];
    float w = g_wn[e];
    const float4 x = *reinterpret_cast<const float4*>(
        &g_Xt[((size_t)p * N_NODES + s) * FDIM + l]);
    float* y = &g_Yt[((size_t)p * N_NODES + d) * FDIM + l];
    atomicAdd(y + 0, w * x.x);   // return unused -> RED (no round trip)
    atomicAdd(y + 1, w * x.y);
    atomicAdd(y + 2, w * x.z);
    atomicAdd(y + 3, w * x.w);
}

// Pack weights: g_W[k][g][j] = (k<64 ? Wx0[gp][k][j] : Wx1[gp][k-64][j]), gp in {0,2,3}
// Combined bias and o-gate peephole.
__global__ void prep_kernel(const float* __restrict__ Wx0, const float* __restrict__ Wx1,
                            const float* __restrict__ bx,  const float* __restrict__ bh,
                            const float* __restrict__ wc,  const float* __restrict__ bg) {
    int idx = blockIdx.x * blockDim.x + threadIdx.x;
    if (idx >= KDIM * NG * FDIM) return;
    int j = idx % FDIM;
    int g = (idx / FDIM) % NG;
    int k = idx / (FDIM * NG);
    const int gmap[NG] = {0, 2, 3};
    int gp = gmap[g];
    float v = (k < FDIM) ? Wx0[((size_t)gp * FDIM + k) * FDIM + j]
                         : Wx1[((size_t)gp * FDIM + (k - FDIM)) * FDIM + j];
    g_W[((size_t)k * NG + g) * FDIM + j] = v;
    if (k == 0) {
        g_bias[g * FDIM + j] = bx[gp * FDIM + j] + bh[gp * FDIM + j] + bg[gp * FDIM + j];
        if (g == 0) g_wc2[j] = wc[2 * FDIM + j];
    }
}

// Fused GEMM + gates + period accumulation.
// Block: 256 threads (16x16). Tile: 128 nodes x 32 j-features x 3 gates.
// Thread: 8 nodes x 2 feats x 3 gates = 48 accumulators.
#define TM 128
#define TJ 32
#define KC 32
__global__ __launch_bounds__(256)
void gemm_gates_kernel(float* __restrict__ out) {
    __shared__ __align__(16) float Ws[KDIM][NG * TJ];   // 48 KB
    __shared__ __align__(16) float Ins[KC][TM + 4];     // ~17 KB

    int tid = threadIdx.x;
    int tx = tid & 15;          // j dimension
    int ty = tid >> 4;          // node dimension
    int n0 = blockIdx.x * TM;
    int jb = blockIdx.y;        // 0 or 1 (which 32 of 64 output feats)

    // Load all weights for this j-tile once (persist across periods)
    for (int i = tid; i < KDIM * NG * TJ; i += 256) {
        int j = i % TJ;
        int g = (i / TJ) % NG;
        int k = i / (TJ * NG);
        Ws[k][g * TJ + j] = g_W[((size_t)k * NG + g) * FDIM + jb * TJ + j];
    }

    int jg = jb * TJ + tx * 2;  // global j base (2 consecutive feats)
    float b_i0 = g_bias[0 * FDIM + jg],  b_i1 = g_bias[0 * FDIM + jg + 1];
    float b_c0 = g_bias[1 * FDIM + jg],  b_c1 = g_bias[1 * FDIM + jg + 1];
    float b_o0 = g_bias[2 * FDIM + jg],  b_o1 = g_bias[2 * FDIM + jg + 1];
    float w2_0 = g_wc2[jg],              w2_1 = g_wc2[jg + 1];

    float outacc[8][2];
#pragma unroll
    for (int i = 0; i < 8; i++) { outacc[i][0] = 0.f; outacc[i][1] = 0.f; }

    for (int p = 0; p < PER; p++) {
        const float* __restrict__ Xp = g_Xt + (size_t)p * N_NODES * FDIM;
        const float* __restrict__ Yp = g_Yt + (size_t)p * N_NODES * FDIM;

        float acc[NG][8][2];
#pragma unroll
        for (int g = 0; g < NG; g++)
#pragma unroll
            for (int i = 0; i < 8; i++) { acc[g][i][0] = 0.f; acc[g][i][1] = 0.f; }

        for (int kb = 0; kb < KDIM; kb += KC) {
            __syncthreads();   // protect Ins reuse (and first-iter weight load)
            // Load 128 x 32 input chunk, transposed into Ins[kloc][node]
            {
                int vec = tid & 7;       // which float4 of the 32-wide chunk
                int r0 = tid >> 3;       // 0..31
                int kg = kb + vec * 4;
#pragma unroll
                for (int rr = r0; rr < TM; rr += 32) {
                    int n = n0 + rr;
                    if (n >= N_NODES) n = N_NODES - 1;
                    float4 v;
                    if (kg < FDIM)
                        v = *reinterpret_cast<const float4*>(&Xp[(size_t)n * FDIM + kg]);
                    else
                        v = *reinterpret_cast<const float4*>(&Yp[(size_t)n * FDIM + (kg - FDIM)]);
                    int kl = vec * 4;
                    Ins[kl + 0][rr] = v.x;
                    Ins[kl + 1][rr] = v.y;
                    Ins[kl + 2][rr] = v.z;
                    Ins[kl + 3][rr] = v.w;
                }
            }
            __syncthreads();

#pragma unroll
            for (int kk = 0; kk < KC; kk++) {
                float4 a0 = *reinterpret_cast<const float4*>(&Ins[kk][ty * 8]);
                float4 a1 = *reinterpret_cast<const float4*>(&Ins[kk][ty * 8 + 4]);
                float a[8] = {a0.x, a0.y, a0.z, a0.w, a1.x, a1.y, a1.z, a1.w};
#pragma unroll
                for (int g = 0; g < NG; g++) {
                    float w0 = Ws[kb + kk][g * TJ + tx * 2];
                    float w1 = Ws[kb + kk][g * TJ + tx * 2 + 1];
#pragma unroll
                    for (int i = 0; i < 8; i++) {
                        acc[g][i][0] += a[i] * w0;
                        acc[g][i][1] += a[i] * w1;
                    }
                }
            }
        }

        // Gate epilogue for this period
#pragma unroll
        for (int i = 0; i < 8; i++) {
            float ai0 = acc[0][i][0] + b_i0, ai1 = acc[0][i][1] + b_i1;
            float ac0 = acc[1][i][0] + b_c0, ac1 = acc[1][i][1] + b_c1;
            float ao0 = acc[2][i][0] + b_o0, ao1 = acc[2][i][1] + b_o1;
            float I0 = sigmoid_f(ai0), I1 = sigmoid_f(ai1);
            float T0 = tanh_f(ac0),    T1 = tanh_f(ac1);
            float C0 = I0 * T0,        C1 = I1 * T1;
            float O0 = sigmoid_f(ao0 + w2_0 * C0);
            float O1 = sigmoid_f(ao1 + w2_1 * C1);
            outacc[i][0] += O0 * tanh_f(C0);
            outacc[i][1] += O1 * tanh_f(C1);
        }
    }

    // Store
#pragma unroll
    for (int i = 0; i < 8; i++) {
        int n = n0 + ty * 8 + i;
        if (n < N_NODES) {
            out[(size_t)n * FDIM + jg]     = outacc[i][0];
            out[(size_t)n * FDIM + jg + 1] = outacc[i][1];
        }
    }
}

// ---------------- launch ------------------------------------------------------
extern "C" void kernel_launch(void* const* d_in, const int* in_sizes, int n_in,
                              void* d_out, int out_size) {
    const float* X   = (const float*)d_in[0];
    const int*   ei  = (const int*)d_in[1];
    const float* ew  = (const float*)d_in[2];
    const float* Wx0 = (const float*)d_in[3];
    const float* Wx1 = (const float*)d_in[4];
    const float* bx  = (const float*)d_in[5];
    // d_in[6], d_in[7]: Wh0, Wh1 unused (H = 0)
    const float* bh  = (const float*)d_in[8];
    const float* wc  = (const float*)d_in[9];
    const float* bg  = (const float*)d_in[10];
    float* out = (float*)d_out;

    // 1) zero scratch
    zero_kernel<<<4096, 256>>>();

    // 2) transpose X -> [p][n][f]
    transpose_kernel<<<(N_NODES * FDIM + 255) / 256, 256>>>(X);

    // 3) degrees
    deg_kernel<<<(E_EDGES + 255) / 256, 256>>>(ei, ew);

    // 4) normalized edge weights
    wn_kernel<<<(E_EDGES + 255) / 256, 256>>>(ei, ew);

    // 5) edge scatter: Y = L_hat X, all periods (z = period)
    {
        dim3 grid((E_EDGES * 16 + 255) / 256, 1, PER);
        scatter_kernel<<<grid, 256>>>(ei);
    }

    // 6) pack weights/biases
    prep_kernel<<<(KDIM * NG * FDIM + 255) / 256, 256>>>(Wx0, Wx1, bx, bh, wc, bg);

    // 7) fused GEMM + gates + period sum
    {
        dim3 grid((N_NODES + TM - 1) / TM, FDIM / TJ);
        gemm_gates_kernel<<<grid, 256>>>(out);
    }
}

// round 4
// speedup vs baseline: 1.6032x; 1.6032x over previous
#include <cuda_runtime.h>
#include <cstdint>

// Problem constants (fixed by the reference)
#define N_NODES 50000
#define FDIM    64
#define PER     8
#define E_EDGES 800000
#define KDIM    128      // 2*FDIM (concat Xp | Yp)
#define NG      3        // gates used: i, c, o  (f gate is dead since C=0)

typedef unsigned long long u64;

// ---------------- scratch (static device memory: no allocs allowed) ----------
__device__ float g_Xt[(size_t)PER * N_NODES * FDIM];   // [p][n][f]  102.4 MB
__device__ float g_Yt[(size_t)PER * N_NODES * FDIM];   // [p][n][f]  102.4 MB
__device__ float g_deg[N_NODES];
__device__ float g_wn[E_EDGES];
__device__ float g_W[KDIM * NG * FDIM];                // [k][g][j]
__device__ float g_bias[NG * FDIM];                    // combined bx+bh+bg per gate
__device__ float g_wc2[FDIM];                          // peephole for o-gate

// ---------------- helpers ----------------------------------------------------
__device__ __forceinline__ float sigmoid_f(float x) { return 1.0f / (1.0f + __expf(-x)); }
__device__ __forceinline__ float tanh_f(float x)    { return 1.0f - 2.0f / (__expf(2.0f * x) + 1.0f); }

__device__ __forceinline__ u64 pack2(float lo, float hi) {
    u64 r; asm("mov.b64 %0, {%1, %2};" : "=l"(r) : "f"(lo), "f"(hi)); return r;
}
__device__ __forceinline__ void unpack2(u64 v, float& lo, float& hi) {
    asm("mov.b64 {%0, %1}, %2;" : "=f"(lo), "=f"(hi) : "l"(v));
}
// d = a * b + d on packed f32x2 (Blackwell FFMA2 — 2x fp32 FMA per instruction)
__device__ __forceinline__ void ffma2(u64& d, u64 a, u64 b) {
    asm("fma.rn.f32x2 %0, %1, %2, %0;" : "+l"(d) : "l"(a), "l"(b));
}

// ---------------- kernels ----------------------------------------------------

// Zero g_Yt (all periods) and g_deg. grid-stride float4.
__global__ void zero_kernel() {
    size_t total4 = (size_t)PER * N_NODES * FDIM / 4;
    size_t stride = (size_t)gridDim.x * blockDim.x;
    float4 z = make_float4(0.f, 0.f, 0.f, 0.f);
    for (size_t i = (size_t)blockIdx.x * blockDim.x + threadIdx.x; i < total4; i += stride) {
        reinterpret_cast<float4*>(g_Yt)[i] = z;
    }
    size_t deg4 = N_NODES / 4;
    for (size_t i = (size_t)blockIdx.x * blockDim.x + threadIdx.x; i < deg4; i += stride) {
        reinterpret_cast<float4*>(g_deg)[i] = z;
    }
}

// Transpose X[n][f][p] -> g_Xt[p][n][f]
__global__ void transpose_kernel(const float* __restrict__ X) {
    int idx = blockIdx.x * blockDim.x + threadIdx.x;   // n*FDIM + f
    if (idx >= N_NODES * FDIM) return;
    int n = idx >> 6;
    int f = idx & 63;
    const float4* xp = reinterpret_cast<const float4*>(X + (size_t)n * FDIM * PER + (size_t)f * PER);
    float4 a = xp[0], b = xp[1];
    float v[PER] = {a.x, a.y, a.z, a.w, b.x, b.y, b.z, b.w};
#pragma unroll
    for (int p = 0; p < PER; p++) {
        g_Xt[(size_t)p * N_NODES * FDIM + (size_t)n * FDIM + f] = v[p];
    }
}

// deg[src] += w   (segment_sum over src)
__global__ void deg_kernel(const int* __restrict__ ei, const float* __restrict__ ew) {
    int e = blockIdx.x * blockDim.x + threadIdx.x;
    if (e >= E_EDGES) return;
    atomicAdd(&g_deg[ei[e]], ew[e]);
}

// wn[e] = -dis[src]*w*dis[dst]
__global__ void wn_kernel(const int* __restrict__ ei, const float* __restrict__ ew) {
    int e = blockIdx.x * blockDim.x + threadIdx.x;
    if (e >= E_EDGES) return;
    int s = ei[e];
    int d = ei[E_EDGES + e];
    float ds = g_deg[s], dd = g_deg[d];
    float is = (ds > 0.f) ? rsqrtf(fmaxf(ds, 1e-12f)) : 0.f;
    float id = (dd > 0.f) ? rsqrtf(fmaxf(dd, 1e-12f)) : 0.f;
    g_wn[e] = -is * ew[e] * id;
}

// Y[p][dst][f] += wn[e] * X[p][src][f]   — 16 threads per edge, one v4 RED each.
// blockIdx.z = period (keeps per-period 12.8MB working set hot in L2 per wave).
__global__ void scatter_kernel(const int* __restrict__ ei) {
    int t = blockIdx.x * blockDim.x + threadIdx.x;
    int e = t >> 4;
    if (e >= E_EDGES) return;
    int l = (t & 15) << 2;        // feature base (0..60 step 4)
    int p = blockIdx.z;
    int s = ei[e];
    int d = ei[E_EDGES + e];
    float w = g_wn[e];
    const float4 x = *reinterpret_cast<const float4*>(
        &g_Xt[((size_t)p * N_NODES + s) * FDIM + l]);
    float* y = &g_Yt[((size_t)p * N_NODES + d) * FDIM + l];
    asm volatile("red.global.add.v4.f32 [%0], {%1, %2, %3, %4};"
                 :: "l"(y), "f"(w * x.x), "f"(w * x.y), "f"(w * x.z), "f"(w * x.w)
                 : "memory");
}

// Pack weights: g_W[k][g][j] = (k<64 ? Wx0[gp][k][j] : Wx1[gp][k-64][j]), gp in {0,2,3}
__global__ void prep_kernel(const float* __restrict__ Wx0, const float* __restrict__ Wx1,
                            const float* __restrict__ bx,  const float* __restrict__ bh,
                            const float* __restrict__ wc,  const float* __restrict__ bg) {
    int idx = blockIdx.x * blockDim.x + threadIdx.x;
    if (idx >= KDIM * NG * FDIM) return;
    int j = idx % FDIM;
    int g = (idx / FDIM) % NG;
    int k = idx / (FDIM * NG);
    const int gmap[NG] = {0, 2, 3};
    int gp = gmap[g];
    float v = (k < FDIM) ? Wx0[((size_t)gp * FDIM + k) * FDIM + j]
                         : Wx1[((size_t)gp * FDIM + (k - FDIM)) * FDIM + j];
    g_W[((size_t)k * NG + g) * FDIM + j] = v;
    if (k == 0) {
        g_bias[g * FDIM + j] = bx[gp * FDIM + j] + bh[gp * FDIM + j] + bg[gp * FDIM + j];
        if (g == 0) g_wc2[j] = wc[2 * FDIM + j];
    }
}

// Fused GEMM + gates + period accumulation, FFMA2 mainloop.
// Block: 256 threads (16x16). Tile: 128 nodes x 32 j-features x 3 gates.
// Accumulator pairs span 2 consecutive NODES (same j) -> loaded directly as u64
// from the node-major shared Ins tile, no per-k repacking of activations.
#define TM 128
#define TJ 32
#define KC 32
__global__ __launch_bounds__(256, 2)
void gemm_gates_kernel(float* __restrict__ out) {
    __shared__ __align__(16) float Ws[KDIM][NG * TJ];   // 48 KB
    __shared__ __align__(16) float Ins[KC][TM + 4];     // ~17 KB

    int tid = threadIdx.x;
    int tx = tid & 15;          // j dimension (2 feats per thread)
    int ty = tid >> 4;          // node dimension (8 nodes per thread)
    int n0 = blockIdx.x * TM;
    int jb = blockIdx.y;        // 0 or 1 (which 32 of 64 output feats)

    // Load all weights for this j-tile once (persist across periods)
    for (int i = tid; i < KDIM * NG * TJ; i += 256) {
        int j = i % TJ;
        int g = (i / TJ) % NG;
        int k = i / (TJ * NG);
        Ws[k][g * TJ + j] = g_W[((size_t)k * NG + g) * FDIM + jb * TJ + j];
    }

    int jg = jb * TJ + tx * 2;  // global j base (2 consecutive feats)
    float b_i0 = g_bias[0 * FDIM + jg],  b_i1 = g_bias[0 * FDIM + jg + 1];
    float b_c0 = g_bias[1 * FDIM + jg],  b_c1 = g_bias[1 * FDIM + jg + 1];
    float b_o0 = g_bias[2 * FDIM + jg],  b_o1 = g_bias[2 * FDIM + jg + 1];
    float w2_0 = g_wc2[jg],              w2_1 = g_wc2[jg + 1];

    float outacc[8][2];
#pragma unroll
    for (int i = 0; i < 8; i++) { outacc[i][0] = 0.f; outacc[i][1] = 0.f; }

    for (int p = 0; p < PER; p++) {
        const float* __restrict__ Xp = g_Xt + (size_t)p * N_NODES * FDIM;
        const float* __restrict__ Yp = g_Yt + (size_t)p * N_NODES * FDIM;

        // accA[g][np] = (node np*2, node np*2+1) for feat jg
        // accB[g][np] = same node pair for feat jg+1
        u64 accA[NG][4], accB[NG][4];
#pragma unroll
        for (int g = 0; g < NG; g++)
#pragma unroll
            for (int np = 0; np < 4; np++) { accA[g][np] = 0ULL; accB[g][np] = 0ULL; }

        for (int kb = 0; kb < KDIM; kb += KC) {
            __syncthreads();   // protect Ins reuse (and first-iter weight load)
            // Load 128 x 32 input chunk, transposed into Ins[kloc][node]
            {
                int vec = tid & 7;       // which float4 of the 32-wide k-chunk
                int r0 = tid >> 3;       // 0..31
                int kg = kb + vec * 4;
#pragma unroll
                for (int rr = r0; rr < TM; rr += 32) {
                    int n = n0 + rr;
                    if (n >= N_NODES) n = N_NODES - 1;
                    float4 v;
                    if (kg < FDIM)
                        v = *reinterpret_cast<const float4*>(&Xp[(size_t)n * FDIM + kg]);
                    else
                        v = *reinterpret_cast<const float4*>(&Yp[(size_t)n * FDIM + (kg - FDIM)]);
                    int kl = vec * 4;
                    Ins[kl + 0][rr] = v.x;
                    Ins[kl + 1][rr] = v.y;
                    Ins[kl + 2][rr] = v.z;
                    Ins[kl + 3][rr] = v.w;
                }
            }
            __syncthreads();

#pragma unroll
            for (int kk = 0; kk < KC; kk++) {
                // 8 consecutive nodes = 4 u64 pairs, straight from shared
                const u64* ap = reinterpret_cast<const u64*>(&Ins[kk][ty * 8]);
                u64 A0 = ap[0], A1 = ap[1], A2 = ap[2], A3 = ap[3];
#pragma unroll
                for (int g = 0; g < NG; g++) {
                    float w0 = Ws[kb + kk][g * TJ + tx * 2];
                    float w1 = Ws[kb + kk][g * TJ + tx * 2 + 1];
                    u64 W0 = pack2(w0, w0);
                    u64 W1 = pack2(w1, w1);
                    ffma2(accA[g][0], A0, W0);  ffma2(accB[g][0], A0, W1);
                    ffma2(accA[g][1], A1, W0);  ffma2(accB[g][1], A1, W1);
                    ffma2(accA[g][2], A2, W0);  ffma2(accB[g][2], A2, W1);
                    ffma2(accA[g][3], A3, W0);  ffma2(accB[g][3], A3, W1);
                }
            }
        }

        // Gate epilogue for this period
#pragma unroll
        for (int np = 0; np < 4; np++) {
            float ai[2], ac[2], ao[2], ai1[2], ac1[2], ao1[2];
            unpack2(accA[0][np], ai[0], ai[1]);   // gate i, feat jg, nodes 2np/2np+1
            unpack2(accA[1][np], ac[0], ac[1]);
            unpack2(accA[2][np], ao[0], ao[1]);
            unpack2(accB[0][np], ai1[0], ai1[1]); // feat jg+1
            unpack2(accB[1][np], ac1[0], ac1[1]);
            unpack2(accB[2][np], ao1[0], ao1[1]);
#pragma unroll
            for (int h = 0; h < 2; h++) {
                int i = np * 2 + h;
                float I0 = sigmoid_f(ai[h]  + b_i0), I1 = sigmoid_f(ai1[h] + b_i1);
                float T0 = tanh_f(ac[h]  + b_c0),    T1 = tanh_f(ac1[h] + b_c1);
                float C0 = I0 * T0,                  C1 = I1 * T1;
                float O0 = sigmoid_f(ao[h]  + b_o0 + w2_0 * C0);
                float O1 = sigmoid_f(ao1[h] + b_o1 + w2_1 * C1);
                outacc[i][0] += O0 * tanh_f(C0);
                outacc[i][1] += O1 * tanh_f(C1);
            }
        }
    }

    // Store
#pragma unroll
    for (int i = 0; i < 8; i++) {
        int n = n0 + ty * 8 + i;
        if (n < N_NODES) {
            out[(size_t)n * FDIM + jg]     = outacc[i][0];
            out[(size_t)n * FDIM + jg + 1] = outacc[i][1];
        }
    }
}

// ---------------- launch ------------------------------------------------------
extern "C" void kernel_launch(void* const* d_in, const int* in_sizes, int n_in,
                              void* d_out, int out_size) {
    const float* X   = (const float*)d_in[0];
    const int*   ei  = (const int*)d_in[1];
    const float* ew  = (const float*)d_in[2];
    const float* Wx0 = (const float*)d_in[3];
    const float* Wx1 = (const float*)d_in[4];
    const float* bx  = (const float*)d_in[5];
    // d_in[6], d_in[7]: Wh0, Wh1 unused (H = 0)
    const float* bh  = (const float*)d_in[8];
    const float* wc  = (const float*)d_in[9];
    const float* bg  = (const float*)d_in[10];
    float* out = (float*)d_out;

    // 1) zero scratch
    zero_kernel<<<4096, 256>>>();

    // 2) transpose X -> [p][n][f]
    transpose_kernel<<<(N_NODES * FDIM + 255) / 256, 256>>>(X);

    // 3) degrees
    deg_kernel<<<(E_EDGES + 255) / 256, 256>>>(ei, ew);

    // 4) normalized edge weights
    wn_kernel<<<(E_EDGES + 255) / 256, 256>>>(ei, ew);

    // 5) edge scatter: Y = L_hat X, all periods (z = period)
    {
        dim3 grid((E_EDGES * 16 + 255) / 256, 1, PER);
        scatter_kernel<<<grid, 256>>>(ei);
    }

    // 6) pack weights/biases
    prep_kernel<<<(KDIM * NG * FDIM + 255) / 256, 256>>>(Wx0, Wx1, bx, bh, wc, bg);

    // 7) fused GEMM + gates + period sum
    {
        dim3 grid((N_NODES + TM - 1) / TM, FDIM / TJ);
        gemm_gates_kernel<<<grid, 256>>>(out);
    }
}

// round 7
// speedup vs baseline: 1.7944x; 1.1193x over previous
#include <cuda_runtime.h>
#include <cstdint>

// Problem constants (fixed by the reference)
#define N_NODES 50000
#define FDIM    64
#define PER     8
#define E_EDGES 800000
#define KDIM    128      // 2*FDIM (concat Xp | Yp)
#define NG      3        // gates used: i, c, o  (f gate is dead since C=0)

typedef unsigned long long u64;

// ---------------- scratch (static device memory: no allocs allowed) ----------
__device__ float g_Xt[(size_t)PER * N_NODES * FDIM];   // [p][n][f]  102.4 MB
__device__ float g_Yt[(size_t)PER * N_NODES * FDIM];   // [p][n][f]  102.4 MB
__device__ float g_deg[N_NODES];                        // weighted out-degree (src)
__device__ int   g_cnt[N_NODES];                        // in-degree count (dst)
__device__ int   g_rowptr[N_NODES + 1];                 // CSR row pointers (by dst)
__device__ int   g_cur[N_NODES];                        // fill cursors
__device__ float g_wn[E_EDGES];                         // normalized weight per edge
__device__ int   g_csrc[E_EDGES];                       // CSR src index
__device__ float g_cw[E_EDGES];                         // CSR edge weight
__device__ float g_W[KDIM * NG * FDIM];                 // [k][g][j]
__device__ float g_bias[NG * FDIM];                     // combined bx+bh+bg per gate
__device__ float g_wc2[FDIM];                           // peephole for o-gate

// ---------------- helpers ----------------------------------------------------
__device__ __forceinline__ float sigmoid_f(float x) { return 1.0f / (1.0f + __expf(-x)); }
__device__ __forceinline__ float tanh_f(float x)    { return 1.0f - 2.0f / (__expf(2.0f * x) + 1.0f); }

__device__ __forceinline__ u64 pack2(float lo, float hi) {
    u64 r; asm("mov.b64 %0, {%1, %2};" : "=l"(r) : "f"(lo), "f"(hi)); return r;
}
__device__ __forceinline__ void unpack2(u64 v, float& lo, float& hi) {
    asm("mov.b64 {%0, %1}, %2;" : "=f"(lo), "=f"(hi) : "l"(v));
}
// d = a * b + d on packed f32x2 (Blackwell FFMA2 — 2x fp32 FMA per instruction)
__device__ __forceinline__ void ffma2(u64& d, u64 a, u64 b) {
    asm("fma.rn.f32x2 %0, %1, %2, %0;" : "+l"(d) : "l"(a), "l"(b));
}

// ---------------- kernels ----------------------------------------------------

// Zero g_deg and g_cnt (Y no longer needs zeroing — gather writes it fully).
__global__ void zero_kernel() {
    int i = blockIdx.x * blockDim.x + threadIdx.x;
    if (i < N_NODES) { g_deg[i] = 0.f; g_cnt[i] = 0; }
}

// Transpose X[n][f][p] -> g_Xt[p][n][f]
__global__ void transpose_kernel(const float* __restrict__ X) {
    int idx = blockIdx.x * blockDim.x + threadIdx.x;   // n*FDIM + f
    if (idx >= N_NODES * FDIM) return;
    int n = idx >> 6;
    int f = idx & 63;
    const float4* xp = reinterpret_cast<const float4*>(X + (size_t)n * FDIM * PER + (size_t)f * PER);
    float4 a = xp[0], b = xp[1];
    float v[PER] = {a.x, a.y, a.z, a.w, b.x, b.y, b.z, b.w};
#pragma unroll
    for (int p = 0; p < PER; p++) {
        g_Xt[(size_t)p * N_NODES * FDIM + (size_t)n * FDIM + f] = v[p];
    }
}

// deg[src] += w  and  cnt[dst] += 1
__global__ void deg_cnt_kernel(const int* __restrict__ ei, const float* __restrict__ ew) {
    int e = blockIdx.x * blockDim.x + threadIdx.x;
    if (e >= E_EDGES) return;
    atomicAdd(&g_deg[ei[e]], ew[e]);
    atomicAdd(&g_cnt[ei[E_EDGES + e]], 1);
}

// wn[e] = -dis[src]*w*dis[dst]
__global__ void wn_kernel(const int* __restrict__ ei, const float* __restrict__ ew) {
    int e = blockIdx.x * blockDim.x + threadIdx.x;
    if (e >= E_EDGES) return;
    int s = ei[e];
    int d = ei[E_EDGES + e];
    float ds = g_deg[s], dd = g_deg[d];
    float is = (ds > 0.f) ? rsqrtf(fmaxf(ds, 1e-12f)) : 0.f;
    float id = (dd > 0.f) ? rsqrtf(fmaxf(dd, 1e-12f)) : 0.f;
    g_wn[e] = -is * ew[e] * id;
}

// Single-block exclusive scan of g_cnt -> g_rowptr (and init g_cur).
__global__ void scan_kernel() {
    __shared__ int sh[1024];
    __shared__ int carry_s;
    int tid = threadIdx.x;
    if (tid == 0) carry_s = 0;
    __syncthreads();
    for (int base = 0; base < N_NODES; base += 1024) {
        int i = base + tid;
        int v = (i < N_NODES) ? g_cnt[i] : 0;
        sh[tid] = v;
        __syncthreads();
        // Hillis-Steele inclusive scan
        for (int off = 1; off < 1024; off <<= 1) {
            int t = (tid >= off) ? sh[tid - off] : 0;
            __syncthreads();
            sh[tid] += t;
            __syncthreads();
        }
        int incl = sh[tid];
        int excl = incl - v;
        int carry = carry_s;
        if (i < N_NODES) {
            g_rowptr[i] = carry + excl;
            g_cur[i]    = carry + excl;
        }
        __syncthreads();
        if (tid == 1023) carry_s = carry + incl;
        __syncthreads();
    }
    if (tid == 0) g_rowptr[N_NODES] = E_EDGES;
}

// Fill CSR (dst-ordered): csrc[pos]=src, cw[pos]=wn[e]
__global__ void fill_kernel(const int* __restrict__ ei) {
    int e = blockIdx.x * blockDim.x + threadIdx.x;
    if (e >= E_EDGES) return;
    int d = ei[E_EDGES + e];
    int pos = atomicAdd(&g_cur[d], 1);
    g_csrc[pos] = ei[e];
    g_cw[pos] = g_wn[e];
}

// Gather: Y[p][n][f] = sum_{e in in(n)} w_e * X[p][src_e][f]
// 16 threads per node (float4 each); blockIdx.z = period (L2-resident slice).
__global__ void gather_kernel() {
    int t = blockIdx.x * blockDim.x + threadIdx.x;
    int node = t >> 4;
    if (node >= N_NODES) return;
    int l = (t & 15) << 2;
    int p = blockIdx.z;
    int beg = g_rowptr[node];
    int end = g_rowptr[node + 1];
    const float* __restrict__ Xp = g_Xt + (size_t)p * N_NODES * FDIM;
    float ax = 0.f, ay = 0.f, az = 0.f, aw = 0.f;
    for (int e = beg; e < end; e++) {
        int s = g_csrc[e];
        float w = g_cw[e];
        float4 x = *reinterpret_cast<const float4*>(&Xp[(size_t)s * FDIM + l]);
        ax += w * x.x; ay += w * x.y; az += w * x.z; aw += w * x.w;
    }
    *reinterpret_cast<float4*>(&g_Yt[((size_t)p * N_NODES + node) * FDIM + l]) =
        make_float4(ax, ay, az, aw);
}

// Pack weights: g_W[k][g][j] = (k<64 ? Wx0[gp][k][j] : Wx1[gp][k-64][j]), gp in {0,2,3}
__global__ void prep_kernel(const float* __restrict__ Wx0, const float* __restrict__ Wx1,
                            const float* __restrict__ bx,  const float* __restrict__ bh,
                            const float* __restrict__ wc,  const float* __restrict__ bg) {
    int idx = blockIdx.x * blockDim.x + threadIdx.x;
    if (idx >= KDIM * NG * FDIM) return;
    int j = idx % FDIM;
    int g = (idx / FDIM) % NG;
    int k = idx / (FDIM * NG);
    const int gmap[NG] = {0, 2, 3};
    int gp = gmap[g];
    float v = (k < FDIM) ? Wx0[((size_t)gp * FDIM + k) * FDIM + j]
                         : Wx1[((size_t)gp * FDIM + (k - FDIM)) * FDIM + j];
    g_W[((size_t)k * NG + g) * FDIM + j] = v;
    if (k == 0) {
        g_bias[g * FDIM + j] = bx[gp * FDIM + j] + bh[gp * FDIM + j] + bg[gp * FDIM + j];
        if (g == 0) g_wc2[j] = wc[2 * FDIM + j];
    }
}

// Fused GEMM + gates + period accumulation, FFMA2 mainloop (identical to R4 winner).
#define TM 128
#define TJ 32
#define KC 32
__global__ __launch_bounds__(256, 2)
void gemm_gates_kernel(float* __restrict__ out) {
    __shared__ __align__(16) float Ws[KDIM][NG * TJ];   // 48 KB
    __shared__ __align__(16) float Ins[KC][TM + 4];     // ~17 KB

    int tid = threadIdx.x;
    int tx = tid & 15;          // j dimension (2 feats per thread)
    int ty = tid >> 4;          // node dimension (8 nodes per thread)
    int n0 = blockIdx.x * TM;
    int jb = blockIdx.y;        // 0 or 1 (which 32 of 64 output feats)

    for (int i = tid; i < KDIM * NG * TJ; i += 256) {
        int j = i % TJ;
        int g = (i / TJ) % NG;
        int k = i / (TJ * NG);
        Ws[k][g * TJ + j] = g_W[((size_t)k * NG + g) * FDIM + jb * TJ + j];
    }

    int jg = jb * TJ + tx * 2;
    float b_i0 = g_bias[0 * FDIM + jg],  b_i1 = g_bias[0 * FDIM + jg + 1];
    float b_c0 = g_bias[1 * FDIM + jg],  b_c1 = g_bias[1 * FDIM + jg + 1];
    float b_o0 = g_bias[2 * FDIM + jg],  b_o1 = g_bias[2 * FDIM + jg + 1];
    float w2_0 = g_wc2[jg],              w2_1 = g_wc2[jg + 1];

    float outacc[8][2];
#pragma unroll
    for (int i = 0; i < 8; i++) { outacc[i][0] = 0.f; outacc[i][1] = 0.f; }

    for (int p = 0; p < PER; p++) {
        const float* __restrict__ Xp = g_Xt + (size_t)p * N_NODES * FDIM;
        const float* __restrict__ Yp = g_Yt + (size_t)p * N_NODES * FDIM;

        u64 accA[NG][4], accB[NG][4];
#pragma unroll
        for (int g = 0; g < NG; g++)
#pragma unroll
            for (int np = 0; np < 4; np++) { accA[g][np] = 0ULL; accB[g][np] = 0ULL; }

        for (int kb = 0; kb < KDIM; kb += KC) {
            __syncthreads();
            {
                int vec = tid & 7;
                int r0 = tid >> 3;
                int kg = kb + vec * 4;
#pragma unroll
                for (int rr = r0; rr < TM; rr += 32) {
                    int n = n0 + rr;
                    if (n >= N_NODES) n = N_NODES - 1;
                    float4 v;
                    if (kg < FDIM)
                        v = *reinterpret_cast<const float4*>(&Xp[(size_t)n * FDIM + kg]);
                    else
                        v = *reinterpret_cast<const float4*>(&Yp[(size_t)n * FDIM + (kg - FDIM)]);
                    int kl = vec * 4;
                    Ins[kl + 0][rr] = v.x;
                    Ins[kl + 1][rr] = v.y;
                    Ins[kl + 2][rr] = v.z;
                    Ins[kl + 3][rr] = v.w;
                }
            }
            __syncthreads();

#pragma unroll
            for (int kk = 0; kk < KC; kk++) {
                const u64* ap = reinterpret_cast<const u64*>(&Ins[kk][ty * 8]);
                u64 A0 = ap[0], A1 = ap[1], A2 = ap[2], A3 = ap[3];
#pragma unroll
                for (int g = 0; g < NG; g++) {
                    float w0 = Ws[kb + kk][g * TJ + tx * 2];
                    float w1 = Ws[kb + kk][g * TJ + tx * 2 + 1];
                    u64 W0 = pack2(w0, w0);
                    u64 W1 = pack2(w1, w1);
                    ffma2(accA[g][0], A0, W0);  ffma2(accB[g][0], A0, W1);
                    ffma2(accA[g][1], A1, W0);  ffma2(accB[g][1], A1, W1);
                    ffma2(accA[g][2], A2, W0);  ffma2(accB[g][2], A2, W1);
                    ffma2(accA[g][3], A3, W0);  ffma2(accB[g][3], A3, W1);
                }
            }
        }

#pragma unroll
        for (int np = 0; np < 4; np++) {
            float ai[2], ac[2], ao[2], ai1[2], ac1[2], ao1[2];
            unpack2(accA[0][np], ai[0], ai[1]);
            unpack2(accA[1][np], ac[0], ac[1]);
            unpack2(accA[2][np], ao[0], ao[1]);
            unpack2(accB[0][np], ai1[0], ai1[1]);
            unpack2(accB[1][np], ac1[0], ac1[1]);
            unpack2(accB[2][np], ao1[0], ao1[1]);
#pragma unroll
            for (int h = 0; h < 2; h++) {
                int i = np * 2 + h;
                float I0 = sigmoid_f(ai[h]  + b_i0), I1 = sigmoid_f(ai1[h] + b_i1);
                float T0 = tanh_f(ac[h]  + b_c0),    T1 = tanh_f(ac1[h] + b_c1);
                float C0 = I0 * T0,                  C1 = I1 * T1;
                float O0 = sigmoid_f(ao[h]  + b_o0 + w2_0 * C0);
                float O1 = sigmoid_f(ao1[h] + b_o1 + w2_1 * C1);
                outacc[i][0] += O0 * tanh_f(C0);
                outacc[i][1] += O1 * tanh_f(C1);
            }
        }
    }

#pragma unroll
    for (int i = 0; i < 8; i++) {
        int n = n0 + ty * 8 + i;
        if (n < N_NODES) {
            out[(size_t)n * FDIM + jg]     = outacc[i][0];
            out[(size_t)n * FDIM + jg + 1] = outacc[i][1];
        }
    }
}

// ---------------- launch ------------------------------------------------------
extern "C" void kernel_launch(void* const* d_in, const int* in_sizes, int n_in,
                              void* d_out, int out_size) {
    const float* X   = (const float*)d_in[0];
    const int*   ei  = (const int*)d_in[1];
    const float* ew  = (const float*)d_in[2];
    const float* Wx0 = (const float*)d_in[3];
    const float* Wx1 = (const float*)d_in[4];
    const float* bx  = (const float*)d_in[5];
    // d_in[6], d_in[7]: Wh0, Wh1 unused (H = 0)
    const float* bh  = (const float*)d_in[8];
    const float* wc  = (const float*)d_in[9];
    const float* bg  = (const float*)d_in[10];
    float* out = (float*)d_out;

    // 1) zero deg/cnt
    zero_kernel<<<(N_NODES + 255) / 256, 256>>>();

    // 2) transpose X -> [p][n][f]
    transpose_kernel<<<(N_NODES * FDIM + 255) / 256, 256>>>(X);

    // 3) weighted out-degree + in-degree counts
    deg_cnt_kernel<<<(E_EDGES + 255) / 256, 256>>>(ei, ew);

    // 4) normalized edge weights
    wn_kernel<<<(E_EDGES + 255) / 256, 256>>>(ei, ew);

    // 5) CSR build: scan + fill
    scan_kernel<<<1, 1024>>>();
    fill_kernel<<<(E_EDGES + 255) / 256, 256>>>(ei);

    // 6) gather: Y = L_hat X, all periods (z = period)
    {
        dim3 grid((N_NODES * 16 + 255) / 256, 1, PER);
        gather_kernel<<<grid, 256>>>();
    }

    // 7) pack weights/biases
    prep_kernel<<<(KDIM * NG * FDIM + 255) / 256, 256>>>(Wx0, Wx1, bx, bh, wc, bg);

    // 8) fused GEMM + gates + period sum
    {
        dim3 grid((N_NODES + TM - 1) / TM, FDIM / TJ);
        gemm_gates_kernel<<<grid, 256>>>(out);
    }
}

// round 12
// speedup vs baseline: 1.9345x; 1.0781x over previous
#include <cuda_runtime.h>
#include <cuda_bf16.h>
#include <cstdint>

// Problem constants (fixed by the reference)
#define N_NODES 50000
#define FDIM    64
#define PER     8
#define E_EDGES 800000

typedef unsigned long long u64;

// ---------------- scratch (static device memory: no allocs allowed) ----------
__device__ float g_Xt[(size_t)PER * N_NODES * FDIM];   // [p][n][f]
__device__ float g_Yt[(size_t)PER * N_NODES * FDIM];   // [p][n][f]
__device__ float g_deg[N_NODES];                        // weighted out-degree (src)
__device__ int   g_cnt[N_NODES];                        // in-degree count (dst)
__device__ int   g_rowptr[N_NODES + 1];                 // CSR row pointers (by dst)
__device__ int   g_cur[N_NODES];                        // fill cursors
__device__ int2  g_cedge[E_EDGES];                      // CSR {src, w-as-int}
// B operand in fragment-interleaved order, bf16 hi/lo split.
// u16 flat index within a jb block (24576 elems):
//   (((split*8 + kstep)*12 + ntile)*32 + lane)*4 + word*2 + half
__device__ __nv_bfloat16 g_Bfrag[2 * 24576];
__device__ float g_bias[3 * FDIM];                      // combined bx+bh+bg (i,c,o)
__device__ float g_wc2[FDIM];                           // peephole for o-gate

// ---------------- helpers ----------------------------------------------------
__device__ __forceinline__ float sigmoid_f(float x) { return 1.0f / (1.0f + __expf(-x)); }
__device__ __forceinline__ float tanh_f(float x)    { return 1.0f - 2.0f / (__expf(2.0f * x) + 1.0f); }

// m16n8k16 bf16 MMA, fp32 accumulate (base PTX sm_80+, safe for compute_103)
__device__ __forceinline__ void mma_bf16(float* c, const uint32_t* a, const uint32_t* b) {
    asm volatile(
        "mma.sync.aligned.m16n8k16.row.col.f32.bf16.bf16.f32 "
        "{%0,%1,%2,%3}, {%4,%5,%6,%7}, {%8,%9}, {%0,%1,%2,%3};"
        : "+f"(c[0]), "+f"(c[1]), "+f"(c[2]), "+f"(c[3])
        : "r"(a[0]), "r"(a[1]), "r"(a[2]), "r"(a[3]), "r"(b[0]), "r"(b[1]));
}

__device__ __forceinline__ uint32_t pack_bf16x2(float lo_elem, float hi_elem) {
    // low 16 bits = first (even-k) element
    unsigned short a = __bfloat16_as_ushort(__float2bfloat16(lo_elem));
    unsigned short b = __bfloat16_as_ushort(__float2bfloat16(hi_elem));
    return (uint32_t)a | ((uint32_t)b << 16);
}

// ---------------- small kernels ----------------------------------------------
__global__ void zero_kernel() {
    int i = blockIdx.x * blockDim.x + threadIdx.x;
    if (i < N_NODES) { g_deg[i] = 0.f; g_cnt[i] = 0; }
}

// Transpose X[n][f][p] -> g_Xt[p][n][f]
__global__ void transpose_kernel(const float* __restrict__ X) {
    int idx = blockIdx.x * blockDim.x + threadIdx.x;
    if (idx >= N_NODES * FDIM) return;
    int n = idx >> 6;
    int f = idx & 63;
    const float4* xp = reinterpret_cast<const float4*>(X + (size_t)n * FDIM * PER + (size_t)f * PER);
    float4 a = xp[0], b = xp[1];
    float v[PER] = {a.x, a.y, a.z, a.w, b.x, b.y, b.z, b.w};
#pragma unroll
    for (int p = 0; p < PER; p++)
        g_Xt[(size_t)p * N_NODES * FDIM + (size_t)n * FDIM + f] = v[p];
}

// deg[src] += w  and  cnt[dst] += 1
__global__ void deg_cnt_kernel(const int* __restrict__ ei, const float* __restrict__ ew) {
    int e = blockIdx.x * blockDim.x + threadIdx.x;
    if (e >= E_EDGES) return;
    atomicAdd(&g_deg[ei[e]], ew[e]);
    atomicAdd(&g_cnt[ei[E_EDGES + e]], 1);
}

// Single-block exclusive scan of g_cnt -> g_rowptr (and init g_cur).
__global__ void scan_kernel() {
    __shared__ int sh[1024];
    __shared__ int carry_s;
    int tid = threadIdx.x;
    if (tid == 0) carry_s = 0;
    __syncthreads();
    for (int base = 0; base < N_NODES; base += 1024) {
        int i = base + tid;
        int v = (i < N_NODES) ? g_cnt[i] : 0;
        sh[tid] = v;
        __syncthreads();
        for (int off = 1; off < 1024; off <<= 1) {
            int t = (tid >= off) ? sh[tid - off] : 0;
            __syncthreads();
            sh[tid] += t;
            __syncthreads();
        }
        int incl = sh[tid];
        int excl = incl - v;
        int carry = carry_s;
        if (i < N_NODES) {
            g_rowptr[i] = carry + excl;
            g_cur[i]    = carry + excl;
        }
        __syncthreads();
        if (tid == 1023) carry_s = carry + incl;
        __syncthreads();
    }
    if (tid == 0) g_rowptr[N_NODES] = E_EDGES;
}

// Fill CSR with inline wn computation: cedge[pos] = {src, -dis[s]*w*dis[d]}
__global__ void fill_kernel(const int* __restrict__ ei, const float* __restrict__ ew) {
    int e = blockIdx.x * blockDim.x + threadIdx.x;
    if (e >= E_EDGES) return;
    int s = ei[e];
    int d = ei[E_EDGES + e];
    float ds = g_deg[s], dd = g_deg[d];
    float is = (ds > 0.f) ? rsqrtf(fmaxf(ds, 1e-12f)) : 0.f;
    float id = (dd > 0.f) ? rsqrtf(fmaxf(dd, 1e-12f)) : 0.f;
    float wn = -is * ew[e] * id;
    int pos = atomicAdd(&g_cur[d], 1);
    g_cedge[pos] = make_int2(s, __float_as_int(wn));
}

// Gather: Y[p][n][f] = sum_{e in in(n)} w_e * X[p][src_e][f]
__global__ void gather_kernel() {
    int t = blockIdx.x * blockDim.x + threadIdx.x;
    int node = t >> 4;
    if (node >= N_NODES) return;
    int l = (t & 15) << 2;
    int p = blockIdx.z;
    int beg = g_rowptr[node];
    int end = g_rowptr[node + 1];
    const float* __restrict__ Xp = g_Xt + (size_t)p * N_NODES * FDIM;
    float ax = 0.f, ay = 0.f, az = 0.f, aw = 0.f;
    for (int e = beg; e < end; e++) {
        int2 sw = g_cedge[e];
        float w = __int_as_float(sw.y);
        float4 x = *reinterpret_cast<const float4*>(&Xp[(size_t)sw.x * FDIM + l]);
        ax += w * x.x; ay += w * x.y; az += w * x.z; aw += w * x.w;
    }
    *reinterpret_cast<float4*>(&g_Yt[((size_t)p * N_NODES + node) * FDIM + l]) =
        make_float4(ax, ay, az, aw);
}

// Build fragment-interleaved bf16 hi/lo B operand + biases/peephole.
// Row order within a jb block: r = g*32 + jj, weight row = gmap[g]*...,
// j = jb*32 + jj. B[k][n=r] = W[r-th out][k].
__global__ void prep_kernel(const float* __restrict__ Wx0, const float* __restrict__ Wx1,
                            const float* __restrict__ bx,  const float* __restrict__ bh,
                            const float* __restrict__ wc,  const float* __restrict__ bg) {
    int idx = blockIdx.x * blockDim.x + threadIdx.x;   // 2 * 96 * 128
    if (idx >= 2 * 96 * 128) return;
    int k   = idx & 127;
    int r   = (idx >> 7) % 96;
    int jb  = idx / (96 * 128);
    int g   = r >> 5;
    int jj  = r & 31;
    int j   = jb * 32 + jj;
    const int gmap[3] = {0, 2, 3};
    int gp = gmap[g];
    float w = (k < FDIM) ? Wx0[((size_t)gp * FDIM + k) * FDIM + j]
                         : Wx1[((size_t)gp * FDIM + (k - FDIM)) * FDIM + j];
    __nv_bfloat16 hi = __float2bfloat16(w);
    __nv_bfloat16 lo = __float2bfloat16(w - __bfloat162float(hi));
    // fragment coords (m16n8k16 B: b0 holds k=(t%4)*2{,+1} at n=t/4; b1: k+8)
    int kstep = k >> 4, kk = k & 15;
    int ntile = r >> 3, nin = r & 7;
    int lane = nin * 4 + ((kk & 7) >> 1);
    int word = kk >> 3;
    int half = kk & 1;
    int base = jb * 24576;
    int off0 = (((0 * 8 + kstep) * 12 + ntile) * 32 + lane) * 4 + word * 2 + half;
    int off1 = (((1 * 8 + kstep) * 12 + ntile) * 32 + lane) * 4 + word * 2 + half;
    g_Bfrag[base + off0] = hi;
    g_Bfrag[base + off1] = lo;
    if (k == 0) {
        g_bias[g * FDIM + j] = bx[gp * FDIM + j] + bh[gp * FDIM + j] + bg[gp * FDIM + j];
        if (g == 0) g_wc2[j] = wc[2 * FDIM + j];
    }
}

// ---------------- tensor-core GEMM + gates + period sum -----------------------
// Grid (391, 2): 128 nodes x 32 j-feats (jb half) x 3 gates = 128 x 96 tile.
// 256 threads = 8 warps in 4(M) x 2(N); warp tile 32 x 48 = 2 m16 x 6 n8 tiles.
// 3-term bf16 split: D = AhiBhi + AhiBlo + AloBhi (fp32 acc, err ~2^-17).
// SMEM: B frags 48KB (persist) + 48KB union {A frags 32KB | stage 128x96 fp32}.
#define SM_B_U32   12288                  // 48KB of u32
#define SMEM_TOTAL (49152 + 49152)

__device__ __forceinline__ int AsIdx(int split, int ks, int mtile, int lane, int word) {
    return (((split * 4 + ks) * 8 + mtile) * 32 + lane) * 4 + word;
}
__device__ __forceinline__ int BsIdx(int split, int kstep, int ntile, int lane, int word) {
    return (((split * 8 + kstep) * 12 + ntile) * 32 + lane) * 2 + word;
}

__global__ __launch_bounds__(256, 2)
void mma_gates_kernel(float* __restrict__ out) {
    extern __shared__ __align__(16) char smem[];
    uint32_t* Bs = reinterpret_cast<uint32_t*>(smem);            // 48KB
    uint32_t* U32 = reinterpret_cast<uint32_t*>(smem + 49152);   // 48KB union
    float* stageF = reinterpret_cast<float*>(smem + 49152);

    int tid = threadIdx.x;
    int wid = tid >> 5;
    int lane = tid & 31;
    int warp_m = wid >> 1;        // 0..3
    int warp_n = wid & 1;         // 0..1
    int n0 = blockIdx.x * 128;
    int jb = blockIdx.y;

    // Load B fragments (already interleaved) into SMEM once.
    {
        const float4* src = reinterpret_cast<const float4*>(g_Bfrag + jb * 24576);
        float4* dst = reinterpret_cast<float4*>(Bs);
        for (int i = tid; i < 24576 * 2 / 16; i += 256) dst[i] = src[i];
    }

    // A-build mapping: each thread converts half a row per chunk.
    int arow = tid >> 1;          // 0..127
    int khalf = tid & 1;          // which 32-k half of the 64-k chunk
    int anode = n0 + arow;
    if (anode >= N_NODES) anode = N_NODES - 1;
    int amtile = arow >> 4;
    int arloc = arow & 15;

    // Epilogue mapping: thread owns (jj = tid&31, nodes w*16..w*16+15)
    int jj = tid & 31;
    int ew_ = tid >> 5;
    int j = jb * 32 + jj;
    float b_i = g_bias[0 * FDIM + j];
    float b_c = g_bias[1 * FDIM + j];
    float b_o = g_bias[2 * FDIM + j];
    float w2  = g_wc2[j];

    float outacc[16];
#pragma unroll
    for (int q = 0; q < 16; q++) outacc[q] = 0.f;

    int gid = lane >> 2;          // fragment group id
    int tig = lane & 3;

    for (int p = 0; p < PER; p++) {
        float acc[2][6][4];
#pragma unroll
        for (int mt = 0; mt < 2; mt++)
#pragma unroll
            for (int nt = 0; nt < 6; nt++)
#pragma unroll
                for (int c = 0; c < 4; c++) acc[mt][nt][c] = 0.f;

#pragma unroll
        for (int chunk = 0; chunk < 2; chunk++) {
            __syncthreads();   // prior MMA/stage use of U done
            // ---- build A frags (bf16 hi/lo) for k in [chunk*64, chunk*64+64) ----
            {
                const float* __restrict__ src =
                    (chunk == 0 ? g_Xt : g_Yt) + ((size_t)p * N_NODES + anode) * FDIM + khalf * 32;
                const float4* src4 = reinterpret_cast<const float4*>(src);
#pragma unroll
                for (int qq = 0; qq < 8; qq++) {
                    float4 v = src4[qq];
                    int kl0 = khalf * 32 + qq * 4;       // chunk-local k of v.x
#pragma unroll
                    for (int pr = 0; pr < 2; pr++) {
                        float u0 = pr ? v.z : v.x;
                        float u1 = pr ? v.w : v.y;
                        int kl = kl0 + pr * 2;
                        int ks = kl >> 4, kk = kl & 15;
                        int ln = (arloc & 7) * 4 + ((kk & 7) >> 1);
                        int wd = (arloc >> 3) + 2 * (kk >> 3);
                        __nv_bfloat16 h0 = __float2bfloat16(u0);
                        __nv_bfloat16 h1 = __float2bfloat16(u1);
                        float l0 = u0 - __bfloat162float(h0);
                        float l1 = u1 - __bfloat162float(h1);
                        uint32_t hw = (uint32_t)__bfloat16_as_ushort(h0) |
                                      ((uint32_t)__bfloat16_as_ushort(h1) << 16);
                        uint32_t lw = pack_bf16x2(l0, l1);
                        U32[AsIdx(0, ks, amtile, ln, wd)] = hw;
                        U32[AsIdx(1, ks, amtile, ln, wd)] = lw;
                    }
                }
            }
            __syncthreads();

            // ---- MMA over 4 k16-steps of this chunk ----
#pragma unroll
            for (int ks = 0; ks < 4; ks++) {
                int ksg = chunk * 4 + ks;
                uint4 aHi[2], aLo[2];
#pragma unroll
                for (int mt = 0; mt < 2; mt++) {
                    int mtile = warp_m * 2 + mt;
                    aHi[mt] = *reinterpret_cast<const uint4*>(&U32[AsIdx(0, ks, mtile, lane, 0)]);
                    aLo[mt] = *reinterpret_cast<const uint4*>(&U32[AsIdx(1, ks, mtile, lane, 0)]);
                }
#pragma unroll
                for (int nt = 0; nt < 6; nt++) {
                    int ntile = warp_n * 6 + nt;
                    uint2 bHi = *reinterpret_cast<const uint2*>(&Bs[BsIdx(0, ksg, ntile, lane, 0)]);
                    uint2 bLo = *reinterpret_cast<const uint2*>(&Bs[BsIdx(1, ksg, ntile, lane, 0)]);
                    uint32_t bh2[2] = {bHi.x, bHi.y};
                    uint32_t bl2[2] = {bLo.x, bLo.y};
#pragma unroll
                    for (int mt = 0; mt < 2; mt++) {
                        const uint32_t* ah = reinterpret_cast<const uint32_t*>(&aHi[mt]);
                        const uint32_t* al = reinterpret_cast<const uint32_t*>(&aLo[mt]);
                        mma_bf16(acc[mt][nt], ah, bh2);
                        mma_bf16(acc[mt][nt], ah, bl2);
                        mma_bf16(acc[mt][nt], al, bh2);
                    }
                }
            }
        }

        // ---- stage preactivations to SMEM (rotated to dodge bank conflicts) ----
        __syncthreads();   // MMA reads of A done before overwriting union
#pragma unroll
        for (int mt = 0; mt < 2; mt++) {
#pragma unroll
            for (int nt = 0; nt < 6; nt++) {
                int r = warp_n * 48 + nt * 8 + tig * 2;
                int nA = warp_m * 32 + mt * 16 + gid;
                int nB = nA + 8;
                int cA = (r + (nA & 7) * 12) % 96;
                int cB = (r + (nB & 7) * 12) % 96;
                *reinterpret_cast<float2*>(&stageF[nA * 96 + cA]) =
                    make_float2(acc[mt][nt][0], acc[mt][nt][1]);
                *reinterpret_cast<float2*>(&stageF[nB * 96 + cB]) =
                    make_float2(acc[mt][nt][2], acc[mt][nt][3]);
            }
        }
        __syncthreads();

        // ---- gate epilogue ----
#pragma unroll
        for (int q = 0; q < 16; q++) {
            int n = ew_ * 16 + q;
            int rot = (n & 7) * 12;
            float vi = stageF[n * 96 + (jj      + rot) % 96] + b_i;
            float vc = stageF[n * 96 + (jj + 32 + rot) % 96] + b_c;
            float vo = stageF[n * 96 + (jj + 64 + rot) % 96] + b_o;
            float I = sigmoid_f(vi);
            float T = tanh_f(vc);
            float C = I * T;
            float O = sigmoid_f(vo + w2 * C);
            outacc[q] += O * tanh_f(C);
        }
    }

    // ---- store ----
#pragma unroll
    for (int q = 0; q < 16; q++) {
        int n = n0 + ew_ * 16 + q;
        if (n < N_NODES) out[(size_t)n * FDIM + j] = outacc[q];
    }
}

// ---------------- launch ------------------------------------------------------
extern "C" void kernel_launch(void* const* d_in, const int* in_sizes, int n_in,
                              void* d_out, int out_size) {
    const float* X   = (const float*)d_in[0];
    const int*   ei  = (const int*)d_in[1];
    const float* ew  = (const float*)d_in[2];
    const float* Wx0 = (const float*)d_in[3];
    const float* Wx1 = (const float*)d_in[4];
    const float* bx  = (const float*)d_in[5];
    // d_in[6], d_in[7]: Wh0, Wh1 unused (H = 0)
    const float* bh  = (const float*)d_in[8];
    const float* wc  = (const float*)d_in[9];
    const float* bg  = (const float*)d_in[10];
    float* out = (float*)d_out;

    cudaFuncSetAttribute(mma_gates_kernel,
                         cudaFuncAttributeMaxDynamicSharedMemorySize, SMEM_TOTAL);

    zero_kernel<<<(N_NODES + 255) / 256, 256>>>();
    transpose_kernel<<<(N_NODES * FDIM + 255) / 256, 256>>>(X);
    deg_cnt_kernel<<<(E_EDGES + 255) / 256, 256>>>(ei, ew);
    scan_kernel<<<1, 1024>>>();
    fill_kernel<<<(E_EDGES + 255) / 256, 256>>>(ei, ew);
    {
        dim3 grid((N_NODES * 16 + 255) / 256, 1, PER);
        gather_kernel<<<grid, 256>>>();
    }
    prep_kernel<<<(2 * 96 * 128 + 255) / 256, 256>>>(Wx0, Wx1, bx, bh, wc, bg);
    {
        dim3 grid((N_NODES + 127) / 128, 2);
        mma_gates_kernel<<<grid, 256, SMEM_TOTAL>>>(out);
    }
}

// round 17
// speedup vs baseline: 2.2300x; 1.1527x over previous
#include <cuda_runtime.h>
#include <cuda_bf16.h>
#include <cstdint>

// Problem constants (fixed by the reference)
#define N_NODES 50000
#define FDIM    64
#define PER     8
#define E_EDGES 800000
#define NBLK    49        // ceil(N_NODES / 1024)

typedef unsigned long long u64;

// ---------------- scratch (static device memory: no allocs allowed) ----------
__device__ float g_Xt[(size_t)PER * N_NODES * FDIM];   // [p][n][f]
__device__ float g_Yt[(size_t)PER * N_NODES * FDIM];   // [p][n][f]
__device__ float g_deg[N_NODES];                        // weighted out-degree (src)
__device__ int   g_cnt[N_NODES];                        // in-degree count (dst)
__device__ int   g_rowptr[N_NODES + 1];                 // CSR row pointers (by dst)
__device__ int   g_cur[N_NODES];                        // fill cursors
__device__ int   g_blksum[64];                          // scan block sums
__device__ int   g_blkoff[64];                          // scan block offsets
__device__ int2  g_cedge[E_EDGES];                      // CSR {src, w-as-int}
// B operand in fragment-interleaved order, bf16 hi/lo split.
__device__ __nv_bfloat16 g_Bfrag[2 * 24576];
__device__ float g_bias[3 * FDIM];                      // combined bx+bh+bg (i,c,o)
__device__ float g_wc2[FDIM];                           // peephole for o-gate

// ---------------- helpers ----------------------------------------------------
__device__ __forceinline__ float sigmoid_f(float x) { return 1.0f / (1.0f + __expf(-x)); }
__device__ __forceinline__ float tanh_f(float x)    { return 1.0f - 2.0f / (__expf(2.0f * x) + 1.0f); }

// m16n8k16 bf16 MMA, fp32 accumulate (base PTX sm_80+, safe for compute_103)
__device__ __forceinline__ void mma_bf16(float* c, const uint32_t* a, const uint32_t* b) {
    asm volatile(
        "mma.sync.aligned.m16n8k16.row.col.f32.bf16.bf16.f32 "
        "{%0,%1,%2,%3}, {%4,%5,%6,%7}, {%8,%9}, {%0,%1,%2,%3};"
        : "+f"(c[0]), "+f"(c[1]), "+f"(c[2]), "+f"(c[3])
        : "r"(a[0]), "r"(a[1]), "r"(a[2]), "r"(a[3]), "r"(b[0]), "r"(b[1]));
}

// ---------------- small kernels ----------------------------------------------
__global__ void zero_kernel() {
    int i = blockIdx.x * blockDim.x + threadIdx.x;
    if (i < N_NODES) { g_deg[i] = 0.f; g_cnt[i] = 0; }
}

// Transpose X[n][f][p] -> g_Xt[p][n][f]
__global__ void transpose_kernel(const float* __restrict__ X) {
    int idx = blockIdx.x * blockDim.x + threadIdx.x;
    if (idx >= N_NODES * FDIM) return;
    int n = idx >> 6;
    int f = idx & 63;
    const float4* xp = reinterpret_cast<const float4*>(X + (size_t)n * FDIM * PER + (size_t)f * PER);
    float4 a = xp[0], b = xp[1];
    float v[PER] = {a.x, a.y, a.z, a.w, b.x, b.y, b.z, b.w};
#pragma unroll
    for (int p = 0; p < PER; p++)
        g_Xt[(size_t)p * N_NODES * FDIM + (size_t)n * FDIM + f] = v[p];
}

// deg[src] += w  and  cnt[dst] += 1
__global__ void deg_cnt_kernel(const int* __restrict__ ei, const float* __restrict__ ew) {
    int e = blockIdx.x * blockDim.x + threadIdx.x;
    if (e >= E_EDGES) return;
    atomicAdd(&g_deg[ei[e]], ew[e]);
    atomicAdd(&g_cnt[ei[E_EDGES + e]], 1);
}

// ---- 3-phase multi-block exclusive scan of g_cnt -> g_rowptr ----
// Phase 1: per-block (1024 elems) warp-shuffle scan; block-local exclusive to
// g_rowptr, block total to g_blksum.
__global__ __launch_bounds__(1024) void scan1_kernel() {
    __shared__ int wsum[32];
    int b = blockIdx.x, tid = threadIdx.x;
    int i = b * 1024 + tid;
    int v = (i < N_NODES) ? g_cnt[i] : 0;
    int x = v;
#pragma unroll
    for (int off = 1; off < 32; off <<= 1) {
        int t = __shfl_up_sync(0xFFFFFFFFu, x, off);
        if ((tid & 31) >= off) x += t;
    }
    if ((tid & 31) == 31) wsum[tid >> 5] = x;
    __syncthreads();
    if (tid < 32) {
        int y = wsum[tid];
#pragma unroll
        for (int off = 1; off < 32; off <<= 1) {
            int t = __shfl_up_sync(0xFFFFFFFFu, y, off);
            if (tid >= off) y += t;
        }
        wsum[tid] = y;
    }
    __syncthreads();
    int base = (tid >= 32) ? wsum[(tid >> 5) - 1] : 0;
    int incl = base + x;
    if (i < N_NODES) g_rowptr[i] = incl - v;
    if (tid == 1023) g_blksum[b] = incl;
}

// Phase 2: exclusive scan of NBLK block sums (tiny).
__global__ void scan2_kernel() {
    int tid = threadIdx.x;
    __shared__ int sh[64];
    sh[tid] = (tid < NBLK) ? g_blksum[tid] : 0;
    __syncthreads();
    if (tid == 0) {
        int run = 0;
        for (int k = 0; k < NBLK; k++) { int t = sh[k]; sh[k] = run; run += t; }
    }
    __syncthreads();
    if (tid < NBLK) g_blkoff[tid] = sh[tid];
}

// Phase 3: add block offsets, init cursors, close rowptr.
__global__ __launch_bounds__(1024) void scan3_kernel() {
    int i = blockIdx.x * 1024 + threadIdx.x;
    if (i < N_NODES) {
        int r = g_rowptr[i] + g_blkoff[blockIdx.x];
        g_rowptr[i] = r;
        g_cur[i] = r;
    }
    if (i == 0) g_rowptr[N_NODES] = E_EDGES;
}

// Fill CSR with inline wn computation: cedge[pos] = {src, -dis[s]*w*dis[d]}
__global__ void fill_kernel(const int* __restrict__ ei, const float* __restrict__ ew) {
    int e = blockIdx.x * blockDim.x + threadIdx.x;
    if (e >= E_EDGES) return;
    int s = ei[e];
    int d = ei[E_EDGES + e];
    float ds = g_deg[s], dd = g_deg[d];
    float is = (ds > 0.f) ? rsqrtf(fmaxf(ds, 1e-12f)) : 0.f;
    float id = (dd > 0.f) ? rsqrtf(fmaxf(dd, 1e-12f)) : 0.f;
    float wn = -is * ew[e] * id;
    int pos = atomicAdd(&g_cur[d], 1);
    g_cedge[pos] = make_int2(s, __float_as_int(wn));
}

// Gather: Y[p][n][f] = sum_{e in in(n)} w_e * X[p][src_e][f]
// 16 threads per node; 2 periods per thread (z = 0..3 handles p=z and p=z+4):
// edge stream read once per 2 periods, 2 independent load chains (MLP).
__global__ void gather_kernel() {
    int t = blockIdx.x * blockDim.x + threadIdx.x;
    int node = t >> 4;
    if (node >= N_NODES) return;
    int l = (t & 15) << 2;
    int p0 = blockIdx.z;
    int p1 = p0 + 4;
    int beg = g_rowptr[node];
    int end = g_rowptr[node + 1];
    const float* __restrict__ X0 = g_Xt + (size_t)p0 * N_NODES * FDIM;
    const float* __restrict__ X1 = g_Xt + (size_t)p1 * N_NODES * FDIM;
    float a0x = 0.f, a0y = 0.f, a0z = 0.f, a0w = 0.f;
    float a1x = 0.f, a1y = 0.f, a1z = 0.f, a1w = 0.f;
    for (int e = beg; e < end; e++) {
        int2 sw = g_cedge[e];
        float w = __int_as_float(sw.y);
        size_t off = (size_t)sw.x * FDIM + l;
        float4 x0 = *reinterpret_cast<const float4*>(&X0[off]);
        float4 x1 = *reinterpret_cast<const float4*>(&X1[off]);
        a0x += w * x0.x; a0y += w * x0.y; a0z += w * x0.z; a0w += w * x0.w;
        a1x += w * x1.x; a1y += w * x1.y; a1z += w * x1.z; a1w += w * x1.w;
    }
    *reinterpret_cast<float4*>(&g_Yt[((size_t)p0 * N_NODES + node) * FDIM + l]) =
        make_float4(a0x, a0y, a0z, a0w);
    *reinterpret_cast<float4*>(&g_Yt[((size_t)p1 * N_NODES + node) * FDIM + l]) =
        make_float4(a1x, a1y, a1z, a1w);
}

// Build fragment-interleaved bf16 hi/lo B operand + biases/peephole.
__global__ void prep_kernel(const float* __restrict__ Wx0, const float* __restrict__ Wx1,
                            const float* __restrict__ bx,  const float* __restrict__ bh,
                            const float* __restrict__ wc,  const float* __restrict__ bg) {
    int idx = blockIdx.x * blockDim.x + threadIdx.x;   // 2 * 96 * 128
    if (idx >= 2 * 96 * 128) return;
    int k   = idx & 127;
    int r   = (idx >> 7) % 96;
    int jb  = idx / (96 * 128);
    int g   = r >> 5;
    int jj  = r & 31;
    int j   = jb * 32 + jj;
    const int gmap[3] = {0, 2, 3};
    int gp = gmap[g];
    float w = (k < FDIM) ? Wx0[((size_t)gp * FDIM + k) * FDIM + j]
                         : Wx1[((size_t)gp * FDIM + (k - FDIM)) * FDIM + j];
    __nv_bfloat16 hi = __float2bfloat16(w);
    __nv_bfloat16 lo = __float2bfloat16(w - __bfloat162float(hi));
    int kstep = k >> 4, kk = k & 15;
    int ntile = r >> 3, nin = r & 7;
    int lane = nin * 4 + ((kk & 7) >> 1);
    int word = kk >> 3;
    int half = kk & 1;
    int base = jb * 24576;
    int off0 = (((0 * 8 + kstep) * 12 + ntile) * 32 + lane) * 4 + word * 2 + half;
    int off1 = (((1 * 8 + kstep) * 12 + ntile) * 32 + lane) * 4 + word * 2 + half;
    g_Bfrag[base + off0] = hi;
    g_Bfrag[base + off1] = lo;
    if (k == 0) {
        g_bias[g * FDIM + j] = bx[gp * FDIM + j] + bh[gp * FDIM + j] + bg[gp * FDIM + j];
        if (g == 0) g_wc2[j] = wc[2 * FDIM + j];
    }
}

// ---------------- tensor-core GEMM + gates + period sum -----------------------
#define SMEM_TOTAL (49152 + 49152)

__device__ __forceinline__ int AsIdx(int split, int ks, int mtile, int lane, int word) {
    return (((split * 4 + ks) * 8 + mtile) * 32 + lane) * 4 + word;
}
__device__ __forceinline__ int BsIdx(int split, int kstep, int ntile, int lane, int word) {
    return (((split * 8 + kstep) * 12 + ntile) * 32 + lane) * 2 + word;
}

__global__ __launch_bounds__(256, 2)
void mma_gates_kernel(float* __restrict__ out) {
    extern __shared__ __align__(16) char smem[];
    uint32_t* Bs = reinterpret_cast<uint32_t*>(smem);            // 48KB
    uint32_t* U32 = reinterpret_cast<uint32_t*>(smem + 49152);   // 48KB union
    float* stageF = reinterpret_cast<float*>(smem + 49152);

    int tid = threadIdx.x;
    int wid = tid >> 5;
    int lane = tid & 31;
    int warp_m = wid >> 1;        // 0..3
    int warp_n = wid & 1;         // 0..1
    int n0 = blockIdx.x * 128;
    int jb = blockIdx.y;

    // Load B fragments (already interleaved) into SMEM once.
    {
        const float4* src = reinterpret_cast<const float4*>(g_Bfrag + jb * 24576);
        float4* dst = reinterpret_cast<float4*>(Bs);
        for (int i = tid; i < 24576 * 2 / 16; i += 256) dst[i] = src[i];
    }

    // A-build mapping: each thread converts half a row per chunk.
    int arow = tid >> 1;          // 0..127
    int khalf = tid & 1;          // which 32-k half of the 64-k chunk
    int anode = n0 + arow;
    if (anode >= N_NODES) anode = N_NODES - 1;
    int amtile = arow >> 4;
    int arloc = arow & 15;

    // Epilogue mapping: thread owns (jj = tid&31, nodes w*16..w*16+15)
    int jj = tid & 31;
    int ew_ = tid >> 5;
    int j = jb * 32 + jj;
    float b_i = g_bias[0 * FDIM + j];
    float b_c = g_bias[1 * FDIM + j];
    float b_o = g_bias[2 * FDIM + j];
    float w2  = g_wc2[j];

    float outacc[16];
#pragma unroll
    for (int q = 0; q < 16; q++) outacc[q] = 0.f;

    int gid = lane >> 2;
    int tig = lane & 3;

    for (int p = 0; p < PER; p++) {
        float acc[2][6][4];
#pragma unroll
        for (int mt = 0; mt < 2; mt++)
#pragma unroll
            for (int nt = 0; nt < 6; nt++)
#pragma unroll
                for (int c = 0; c < 4; c++) acc[mt][nt][c] = 0.f;

#pragma unroll
        for (int chunk = 0; chunk < 2; chunk++) {
            __syncthreads();   // prior MMA/stage use of U done
            // ---- build A frags (bf16 hi/lo) for k in [chunk*64, chunk*64+64) ----
            {
                const float* __restrict__ src =
                    (chunk == 0 ? g_Xt : g_Yt) + ((size_t)p * N_NODES + anode) * FDIM + khalf * 32;
                const float4* src4 = reinterpret_cast<const float4*>(src);
#pragma unroll
                for (int qq = 0; qq < 8; qq++) {
                    float4 v = src4[qq];
                    int kl0 = khalf * 32 + qq * 4;
#pragma unroll
                    for (int pr = 0; pr < 2; pr++) {
                        float u0 = pr ? v.z : v.x;
                        float u1 = pr ? v.w : v.y;
                        int kl = kl0 + pr * 2;
                        int ks = kl >> 4, kk = kl & 15;
                        int ln = (arloc & 7) * 4 + ((kk & 7) >> 1);
                        int wd = (arloc >> 3) + 2 * (kk >> 3);
                        // fast split: one packed cvt for hi, unpack, sub, packed cvt for lo
                        __nv_bfloat162 h2 = __floats2bfloat162_rn(u0, u1);
                        float2 hf = __bfloat1622float2(h2);
                        __nv_bfloat162 l2 = __floats2bfloat162_rn(u0 - hf.x, u1 - hf.y);
                        U32[AsIdx(0, ks, amtile, ln, wd)] = *reinterpret_cast<uint32_t*>(&h2);
                        U32[AsIdx(1, ks, amtile, ln, wd)] = *reinterpret_cast<uint32_t*>(&l2);
                    }
                }
            }
            __syncthreads();

            // ---- MMA over 4 k16-steps of this chunk ----
#pragma unroll
            for (int ks = 0; ks < 4; ks++) {
                int ksg = chunk * 4 + ks;
                uint4 aHi[2], aLo[2];
#pragma unroll
                for (int mt = 0; mt < 2; mt++) {
                    int mtile = warp_m * 2 + mt;
                    aHi[mt] = *reinterpret_cast<const uint4*>(&U32[AsIdx(0, ks, mtile, lane, 0)]);
                    aLo[mt] = *reinterpret_cast<const uint4*>(&U32[AsIdx(1, ks, mtile, lane, 0)]);
                }
#pragma unroll
                for (int nt = 0; nt < 6; nt++) {
                    int ntile = warp_n * 6 + nt;
                    uint2 bHi = *reinterpret_cast<const uint2*>(&Bs[BsIdx(0, ksg, ntile, lane, 0)]);
                    uint2 bLo = *reinterpret_cast<const uint2*>(&Bs[BsIdx(1, ksg, ntile, lane, 0)]);
                    uint32_t bh2[2] = {bHi.x, bHi.y};
                    uint32_t bl2[2] = {bLo.x, bLo.y};
#pragma unroll
                    for (int mt = 0; mt < 2; mt++) {
                        const uint32_t* ah = reinterpret_cast<const uint32_t*>(&aHi[mt]);
                        const uint32_t* al = reinterpret_cast<const uint32_t*>(&aLo[mt]);
                        mma_bf16(acc[mt][nt], ah, bh2);
                        mma_bf16(acc[mt][nt], ah, bl2);
                        mma_bf16(acc[mt][nt], al, bh2);
                    }
                }
            }
        }

        // ---- stage preactivations to SMEM (rotated to dodge bank conflicts) ----
        __syncthreads();
#pragma unroll
        for (int mt = 0; mt < 2; mt++) {
#pragma unroll
            for (int nt = 0; nt < 6; nt++) {
                int r = warp_n * 48 + nt * 8 + tig * 2;
                int nA = warp_m * 32 + mt * 16 + gid;
                int nB = nA + 8;
                int cA = (r + (nA & 7) * 12) % 96;
                int cB = (r + (nB & 7) * 12) % 96;
                *reinterpret_cast<float2*>(&stageF[nA * 96 + cA]) =
                    make_float2(acc[mt][nt][0], acc[mt][nt][1]);
                *reinterpret_cast<float2*>(&stageF[nB * 96 + cB]) =
                    make_float2(acc[mt][nt][2], acc[mt][nt][3]);
            }
        }
        __syncthreads();

        // ---- gate epilogue ----
#pragma unroll
        for (int q = 0; q < 16; q++) {
            int n = ew_ * 16 + q;
            int rot = (n & 7) * 12;
            float vi = stageF[n * 96 + (jj      + rot) % 96] + b_i;
            float vc = stageF[n * 96 + (jj + 32 + rot) % 96] + b_c;
            float vo = stageF[n * 96 + (jj + 64 + rot) % 96] + b_o;
            float I = sigmoid_f(vi);
            float T = tanh_f(vc);
            float C = I * T;
            float O = sigmoid_f(vo + w2 * C);
            outacc[q] += O * tanh_f(C);
        }
    }

    // ---- store ----
#pragma unroll
    for (int q = 0; q < 16; q++) {
        int n = n0 + ew_ * 16 + q;
        if (n < N_NODES) out[(size_t)n * FDIM + j] = outacc[q];
    }
}

// ---------------- launch ------------------------------------------------------
extern "C" void kernel_launch(void* const* d_in, const int* in_sizes, int n_in,
                              void* d_out, int out_size) {
    const float* X   = (const float*)d_in[0];
    const int*   ei  = (const int*)d_in[1];
    const float* ew  = (const float*)d_in[2];
    const float* Wx0 = (const float*)d_in[3];
    const float* Wx1 = (const float*)d_in[4];
    const float* bx  = (const float*)d_in[5];
    // d_in[6], d_in[7]: Wh0, Wh1 unused (H = 0)
    const float* bh  = (const float*)d_in[8];
    const float* wc  = (const float*)d_in[9];
    const float* bg  = (const float*)d_in[10];
    float* out = (float*)d_out;

    cudaFuncSetAttribute(mma_gates_kernel,
                         cudaFuncAttributeMaxDynamicSharedMemorySize, SMEM_TOTAL);

    zero_kernel<<<(N_NODES + 255) / 256, 256>>>();
    transpose_kernel<<<(N_NODES * FDIM + 255) / 256, 256>>>(X);
    deg_cnt_kernel<<<(E_EDGES + 255) / 256, 256>>>(ei, ew);
    scan1_kernel<<<NBLK, 1024>>>();
    scan2_kernel<<<1, 64>>>();
    scan3_kernel<<<NBLK, 1024>>>();
    fill_kernel<<<(E_EDGES + 255) / 256, 256>>>(ei, ew);
    {
        dim3 grid((N_NODES * 16 + 255) / 256, 1, 4);
        gather_kernel<<<grid, 256>>>();
    }
    prep_kernel<<<(2 * 96 * 128 + 255) / 256, 256>>>(Wx0, Wx1, bx, bh, wc, bg);
    {
        dim3 grid((N_NODES + 127) / 128, 2);
        mma_gates_kernel<<<grid, 256, SMEM_TOTAL>>>(out);
    }
}